// round 1
// baseline (speedup 1.0000x reference)
#include <cuda_runtime.h>
#include <cuda_bf16.h>

// SurvivalGeometryRegularizer: out = sum_{i,j} relu(1 + r_i - r_j) * [t_i < t_j] * [e_i==1] / count
// Inputs (metadata order): z [8192*128] f32 (UNUSED), risk [8192] f32, time [8192] f32, event [8192] i32
// Output: 1 float.

#define NB        8192
#define THREADS   256
#define IPT       2
#define TILE_I    (THREADS * IPT)   // 512 i per block tile
#define GY        (NB / TILE_I)     // 16 i-tiles (covers worst case E = 8192)
#define GX        32                // j splits
#define JCHUNK    (NB / GX)         // 256 j per chunk
#define NBLK      (GX * GY)         // 512 blocks

// Scratch (no cudaMalloc allowed): device globals.
__device__ float g_tC[NB];          // compacted time for event==1 rows, padded with +INF
__device__ float g_aC[NB];          // compacted (1 + risk), padded with 0
__device__ int   g_E;               // number of event==1 rows
__device__ float g_part_sum[NBLK];
__device__ float g_part_cnt[NBLK];

// ---------------------------------------------------------------------------
// Kernel 1: deterministic stable compaction of rows with event==1.
// 1 block, 1024 threads, 8 rows/thread, block-wide exclusive scan.
// ---------------------------------------------------------------------------
__global__ __launch_bounds__(1024)
void compact_k(const float* __restrict__ risk,
               const float* __restrict__ tim,
               const int*   __restrict__ event) {
    __shared__ int s_warp[32];
    __shared__ int s_total;

    const int tid  = threadIdx.x;
    const int lane = tid & 31;
    const int warp = tid >> 5;
    const int PER  = NB / 1024;     // 8

    int   flags[PER];
    float tv[PER], rv[PER];
    int local = 0;
    const int base = tid * PER;
#pragma unroll
    for (int p = 0; p < PER; p++) {
        int e    = event[base + p];
        tv[p]    = tim[base + p];
        rv[p]    = risk[base + p];
        flags[p] = e;
        local   += e;
    }

    // warp-level inclusive scan of per-thread totals
    int incl = local;
#pragma unroll
    for (int off = 1; off < 32; off <<= 1) {
        int n = __shfl_up_sync(0xFFFFFFFFu, incl, off);
        if (lane >= off) incl += n;
    }
    if (lane == 31) s_warp[warp] = incl;
    __syncthreads();

    if (warp == 0) {
        int v = s_warp[lane];
        int inc = v;
#pragma unroll
        for (int off = 1; off < 32; off <<= 1) {
            int n = __shfl_up_sync(0xFFFFFFFFu, inc, off);
            if (lane >= off) inc += n;
        }
        s_warp[lane] = inc - v;           // exclusive warp offsets
        if (lane == 31) s_total = inc;    // total E
    }
    __syncthreads();

    int pos = s_warp[warp] + (incl - local);  // exclusive position of this thread's first flagged row
#pragma unroll
    for (int p = 0; p < PER; p++) {
        if (flags[p]) {
            g_tC[pos] = tv[p];
            g_aC[pos] = 1.0f + rv[p];
            pos++;
        }
    }

    const int E = s_total;
    if (tid == 0) g_E = E;
    // Pad tail with sentinels: t=+INF (never satisfies t_i < t_j), a=0 (irrelevant).
    for (int i = E + tid; i < NB; i += 1024) {
        g_tC[i] = __int_as_float(0x7F800000);   // +INF
        g_aC[i] = 0.0f;
    }
}

// ---------------------------------------------------------------------------
// Kernel 2: pair loop. Block (bx, by) handles i-tile by and j-chunk bx.
// time >= 0 always, so t_i < t_j <=> int-bit compare (pushes compare to ALU pipe).
// ---------------------------------------------------------------------------
__global__ __launch_bounds__(THREADS)
void pairs_k(const float* __restrict__ risk,
             const float* __restrict__ tim) {
    __shared__ float2 sj[JCHUNK];
    __shared__ float  s_sum[THREADS];
    __shared__ float  s_cnt[THREADS];

    const int tid   = threadIdx.x;
    const int E     = g_E;
    const int tile0 = blockIdx.y * TILE_I;

    float sum = 0.0f;
    int   cnt = 0;

    if (tile0 < E) {  // uniform branch per block
        int   tib[IPT];
        float ai[IPT];
#pragma unroll
        for (int k = 0; k < IPT; k++) {
            const int idx = tile0 + tid + k * THREADS;   // always < NB by construction
            tib[k] = __float_as_int(g_tC[idx]);
            ai[k]  = g_aC[idx];
        }

        const int j0 = blockIdx.x * JCHUNK;
        for (int j = tid; j < JCHUNK; j += THREADS)
            sj[j] = make_float2(tim[j0 + j], risk[j0 + j]);
        __syncthreads();

#pragma unroll 8
        for (int j = 0; j < JCHUNK; j++) {
            const float2 v  = sj[j];          // broadcast (conflict-free)
            const int   tjb = __float_as_int(v.x);
            const float rj  = v.y;
#pragma unroll
            for (int k = 0; k < IPT; k++) {
                const float h = fmaxf(ai[k] - rj, 0.0f);
                if (tib[k] < tjb) { sum += h; cnt++; }
            }
        }
    }

    // deterministic block reduction
    s_sum[tid] = sum;
    s_cnt[tid] = (float)cnt;
    __syncthreads();
#pragma unroll
    for (int s = THREADS / 2; s > 0; s >>= 1) {
        if (tid < s) {
            s_sum[tid] += s_sum[tid + s];
            s_cnt[tid] += s_cnt[tid + s];
        }
        __syncthreads();
    }
    if (tid == 0) {
        const int b = blockIdx.y * GX + blockIdx.x;
        g_part_sum[b] = s_sum[0];
        g_part_cnt[b] = s_cnt[0];
    }
}

// ---------------------------------------------------------------------------
// Kernel 3: final deterministic reduction over 512 block partials.
// ---------------------------------------------------------------------------
__global__ __launch_bounds__(NBLK)
void final_k(float* __restrict__ out) {
    __shared__ float s_sum[NBLK];
    __shared__ float s_cnt[NBLK];
    const int tid = threadIdx.x;
    s_sum[tid] = g_part_sum[tid];
    s_cnt[tid] = g_part_cnt[tid];
    __syncthreads();
#pragma unroll
    for (int s = NBLK / 2; s > 0; s >>= 1) {
        if (tid < s) {
            s_sum[tid] += s_sum[tid + s];
            s_cnt[tid] += s_cnt[tid + s];
        }
        __syncthreads();
    }
    if (tid == 0)
        out[0] = (s_cnt[0] > 0.0f) ? (s_sum[0] / s_cnt[0]) : 0.0f;
}

extern "C" void kernel_launch(void* const* d_in, const int* in_sizes, int n_in,
                              void* d_out, int out_size) {
    // metadata order: z (unused), risk, time, event
    const float* risk  = (const float*)d_in[1];
    const float* tim   = (const float*)d_in[2];
    const int*   event = (const int*)d_in[3];
    float* out = (float*)d_out;

    compact_k<<<1, 1024>>>(risk, tim, event);
    dim3 grid(GX, GY);
    pairs_k<<<grid, THREADS>>>(risk, tim);
    final_k<<<1, NBLK>>>(out);
}